// round 16
// baseline (speedup 1.0000x reference)
#include <cuda_runtime.h>
#include <math.h>

#define C_ 10
#define Q_ 1000
#define R_ 1024
#define N_ 512
#define S_ 10000
#define M_ 10000          // C_*Q_
#define MP 10240          // padded rows (zero-filled)
#define KSPLIT 8
#define CHUNKP 1280       // MP/KSPLIT
#define SSTR 136          // SYRK SMEM row stride (floats)
#define TILEF (32*SSTR)
#define SYRK_SMEM (4*TILEF*4)   // 69632 bytes
#define CHB 120           // persistent-Cholesky blocks

// ---------------- static device scratch ----------------
static __device__ float g_D[MP * R_];                  // CENTERED queues (padded)
static __device__ float g_Gp[KSPLIT][R_ * R_];
static __device__ float g_S[R_ * R_];
static __device__ float g_mu[C_ * R_];
static __device__ float g_scores[N_ * C_];
static __device__ float g_scores_vos[C_ * C_];
static __device__ float g_eps_sel[C_ * R_];
static __device__ float g_vos[C_ * R_];
static __device__ float g_focal[N_];
static __device__ int   g_order[C_ * N_];
static __device__ int   g_cnt[C_];
static __device__ unsigned long long g_amax[C_];
static __device__ int   g_bars[64];

// ---------------- kernel 1: ordering + counts + state reset + per-class mean ----------------
// block 0: sequential-queue ordering, counts, replay-state reset
// blocks 1..40: mu for (class, col-quarter) computed straight from id_data+box
__global__ void order_mu_kernel(const int* __restrict__ labels,
                                const float* __restrict__ id_data,
                                const float* __restrict__ box) {
    __shared__ int labs[N_];
    int tid = threadIdx.x;                    // 256 threads
    labs[tid] = labels[tid];
    labs[tid + 256] = labels[tid + 256];
    __syncthreads();

    if (blockIdx.x == 0) {
        for (int s = tid; s < N_; s += 256) {
            int lab = labs[s], pos = 0;
            for (int j = 0; j < s; j++) pos += (labs[j] == lab) ? 1 : 0;
            g_order[lab * N_ + pos] = s;
        }
        if (tid < C_) {
            int cnt = 0;
            for (int j = 0; j < N_; j++) cnt += (labs[j] == tid) ? 1 : 0;
            g_cnt[tid] = cnt;
            g_amax[tid] = 0ull;
        }
        if (tid < 64) g_bars[tid] = 0;
        return;
    }
    int b = blockIdx.x - 1;                   // 0..39
    int cls = b >> 2, qt = b & 3;
    int col = qt * 256 + tid;
    int k = 0;
    for (int j = 0; j < N_; j++) k += (labs[j] == cls) ? 1 : 0;
    float s0 = 0.f, s1 = 0.f, s2 = 0.f, s3 = 0.f;
    const float* base = id_data + ((size_t)cls * Q_) * R_ + col;
    int q = k;
    for (; q + 4 <= Q_; q += 4) {
        s0 += base[(size_t)q * R_];
        s1 += base[(size_t)(q + 1) * R_];
        s2 += base[(size_t)(q + 2) * R_];
        s3 += base[(size_t)(q + 3) * R_];
    }
    for (; q < Q_; q++) s0 += base[(size_t)q * R_];
    float s = (s0 + s1) + (s2 + s3);
    for (int j = 0; j < N_; j++)
        if (labs[j] == cls) s += box[(size_t)j * R_ + col];
    g_mu[cls * R_ + col] = s * (1.f / (float)Q_);
}

// ---------------- kernel 2: materialize CENTERED queues (padded with zeros) ----------------
__global__ void matD_kernel(const float* __restrict__ id_data, const float* __restrict__ box) {
    int row = blockIdx.x;
    float4* dst = (float4*)(g_D + (size_t)row * R_);
    if (row >= M_) { dst[threadIdx.x] = make_float4(0.f, 0.f, 0.f, 0.f); return; }
    int c = row / Q_, q = row - c * Q_;
    int k = g_cnt[c];
    const float* src;
    if (q < Q_ - k) src = id_data + (size_t)(c * Q_ + q + k) * R_;
    else            src = box + (size_t)g_order[c * N_ + q - (Q_ - k)] * R_;
    float4 v = ((const float4*)src)[threadIdx.x];
    float4 m = ((const float4*)(g_mu + c * R_))[threadIdx.x];
    dst[threadIdx.x] = make_float4(v.x - m.x, v.y - m.y, v.z - m.z, v.w - m.w);
}

// ---------------- kernel 3: tf32 tensor-core SYRK (cp.async double buffered) ----------------
__device__ __forceinline__ unsigned f2tf(float x) {
    unsigned r; asm("cvt.rna.tf32.f32 %0, %1;" : "=r"(r) : "f"(x)); return r;
}
__device__ __forceinline__ void mma_tf32(float* d, const unsigned* a, const unsigned* b) {
    asm volatile(
        "mma.sync.aligned.m16n8k8.row.col.f32.tf32.tf32.f32 "
        "{%0,%1,%2,%3}, {%4,%5,%6,%7}, {%8,%9}, {%0,%1,%2,%3};\n"
        : "+f"(d[0]), "+f"(d[1]), "+f"(d[2]), "+f"(d[3])
        : "r"(a[0]), "r"(a[1]), "r"(a[2]), "r"(a[3]), "r"(b[0]), "r"(b[1]));
}
__device__ __forceinline__ void cpasync16(unsigned saddr, const void* g) {
    asm volatile("cp.async.ca.shared.global [%0], [%1], 16;\n" :: "r"(saddr), "l"(g));
}
__device__ __forceinline__ void cp_commit() { asm volatile("cp.async.commit_group;\n"); }
__device__ __forceinline__ void cp_wait0()  { asm volatile("cp.async.wait_group 0;\n"); }

__global__ __launch_bounds__(256, 2) void syrk_kernel() {
    extern __shared__ float smem[];
    int t = blockIdx.x;
    int bi = 0;
    while ((bi + 1) * (bi + 2) / 2 <= t) bi++;
    int bj = t - bi * (bi + 1) / 2;
    bool diag = (bi == bj);

    int tid = threadIdx.x;
    int wid = tid >> 5, lane = tid & 31;
    int wy = wid & 1, wx = wid >> 1;
    int g = lane >> 2, tg = lane & 3;
    int lr = tid >> 3, lc = tid & 7;
    int m0 = blockIdx.y * CHUNKP;

    float acc[4][4][4];
#pragma unroll
    for (int mf = 0; mf < 4; mf++)
#pragma unroll
        for (int nf = 0; nf < 4; nf++)
#pragma unroll
            for (int q = 0; q < 4; q++) acc[mf][nf][q] = 0.f;

    auto issue = [&](int b, int mb) {
        float* SA = smem + b * (2 * TILEF);
        float* SB = SA + TILEF;
        const float* gr = g_D + (size_t)(mb + lr) * R_;
        unsigned sA = (unsigned)__cvta_generic_to_shared(SA + lr * SSTR);
        unsigned sB = (unsigned)__cvta_generic_to_shared(SB + lr * SSTR);
#pragma unroll
        for (int i = 0; i < 4; i++) {
            int c0 = (lc + 8 * i) * 4;
            cpasync16(sA + c0 * 4, gr + bi * 128 + c0);
            if (!diag) cpasync16(sB + c0 * 4, gr + bj * 128 + c0);
        }
        cp_commit();
    };

    issue(0, m0);
    for (int s = 0; s < 40; s++) {
        int b = s & 1;
        cp_wait0();
        __syncthreads();
        if (s < 39) issue(b ^ 1, m0 + (s + 1) * 32);
        float* SA = smem + b * (2 * TILEF);
        float* SB = diag ? SA : (SA + TILEF);
#pragma unroll
        for (int ks = 0; ks < 4; ks++) {
            int k0 = ks * 8;
            unsigned af[4][4], bf[4][2];
#pragma unroll
            for (int mf = 0; mf < 4; mf++) {
                int r0 = wy * 64 + mf * 16;
                af[mf][0] = f2tf(SA[(k0 + tg) * SSTR + r0 + g]);
                af[mf][1] = f2tf(SA[(k0 + tg) * SSTR + r0 + g + 8]);
                af[mf][2] = f2tf(SA[(k0 + tg + 4) * SSTR + r0 + g]);
                af[mf][3] = f2tf(SA[(k0 + tg + 4) * SSTR + r0 + g + 8]);
            }
#pragma unroll
            for (int nf = 0; nf < 4; nf++) {
                int c0 = wx * 32 + nf * 8;
                bf[nf][0] = f2tf(SB[(k0 + tg) * SSTR + c0 + g]);
                bf[nf][1] = f2tf(SB[(k0 + tg + 4) * SSTR + c0 + g]);
            }
#pragma unroll
            for (int mf = 0; mf < 4; mf++)
#pragma unroll
                for (int nf = 0; nf < 4; nf++)
                    mma_tf32(acc[mf][nf], af[mf], bf[nf]);
        }
        __syncthreads();
    }
    float* gp = g_Gp[blockIdx.y];
#pragma unroll
    for (int mf = 0; mf < 4; mf++) {
        int r0 = bi * 128 + wy * 64 + mf * 16 + g;
#pragma unroll
        for (int nf = 0; nf < 4; nf++) {
            int c0 = bj * 128 + wx * 32 + nf * 8 + 2 * tg;
            *(float2*)&gp[(size_t)r0 * R_ + c0]       = make_float2(acc[mf][nf][0], acc[mf][nf][1]);
            *(float2*)&gp[(size_t)(r0 + 8) * R_ + c0] = make_float2(acc[mf][nf][2], acc[mf][nf][3]);
        }
    }
}

// ---------------- kernel 4: fused sigma + persistent blocked Cholesky ----------------
__device__ __forceinline__ void grid_bar(int id) {
    __syncthreads();
    if (threadIdx.x == 0) {
        __threadfence();
        atomicAdd(&g_bars[id], 1);
        while (*(volatile int*)&g_bars[id] < CHB) { }
        __threadfence();
    }
    __syncthreads();
}

__global__ __launch_bounds__(256) void chol_kernel() {
    __shared__ float P[64][65];
    __shared__ float rs[64];        // rsqrt of pivots == 1/L[j][j]
    __shared__ float As[64][65];
    __shared__ float Bs[64][65];
    int bid = blockIdx.x, tid = threadIdx.x;

    // ---- fused sigma (lower) = sum Gp / M + 1e-4 I ----
    for (int i = bid; i < R_; i += CHB) {
        size_t ro = (size_t)i * R_;
        for (int j = tid; j <= i; j += 256) {
            float s = 0.f;
#pragma unroll
            for (int z = 0; z < KSPLIT; z++) s += g_Gp[z][ro + j];
            float v = s * (1.f / (float)M_);
            if (i == j) v += 1e-4f;
            g_S[ro + j] = v;
        }
    }
    grid_bar(0);

    int barid = 1;
    for (int p = 0; p < 16; p++) {
        int o = p * 64, o2 = o + 64, nr = R_ - o2;

        if (bid < 4) {
            // load diag panel
            for (int idx = tid; idx < 4096; idx += 256) {
                int i = idx >> 6, j = idx & 63;
                P[i][j] = (j <= i) ? g_S[(size_t)(o + i) * R_ + o + j] : 0.f;
            }
            __syncthreads();
            // 1-sync-per-k potf2: raw rank-1 updates, scaling deferred
            for (int k = 0; k < 64; k++) {
                float d = P[k][k];
                float rd = __frcp_rn(d);
                if (tid == 0) rs[k] = rsqrtf(d);
                int n = 63 - k;
                for (int idx = tid; idx < n * 64; idx += 256) {
                    int i2 = k + 1 + (idx >> 6);
                    int j2 = idx & 63;
                    if (j2 > k && j2 <= i2) P[i2][j2] -= P[i2][k] * P[j2][k] * rd;
                }
                __syncthreads();
            }
            // finalize: column scaling -> L
            for (int idx = tid; idx < 4096; idx += 256) {
                int i = idx >> 6, j = idx & 63;
                if (j <= i) P[i][j] *= rs[j];
            }
            __syncthreads();
            if (bid == 0) {
                for (int idx = tid; idx < 4096; idx += 256) {
                    int i = idx >> 6, j = idx & 63;
                    if (j <= i) g_S[(size_t)(o + i) * R_ + o + j] = P[i][j];
                }
            }
            // TRSM rows (named-register 8-col blocks)
            if (nr > 0) {
                int rr = bid * 256 + tid;
                if (rr < nr) {
                    int r = o2 + rr;
                    float* gptr = g_S + (size_t)r * R_ + o;
#pragma unroll
                    for (int b = 0; b < 8; b++) {
                        float* gb = gptr + b * 8;
                        float x0 = gb[0], x1 = gb[1], x2 = gb[2], x3 = gb[3],
                              x4 = gb[4], x5 = gb[5], x6 = gb[6], x7 = gb[7];
#pragma unroll
                        for (int kb = 0; kb < b; kb++) {
                            const float* hp = gptr + kb * 8;
                            float h0 = hp[0], h1 = hp[1], h2 = hp[2], h3 = hp[3],
                                  h4 = hp[4], h5 = hp[5], h6 = hp[6], h7 = hp[7];
#define UPDJ(j) { const float* Lj = &P[b * 8 + (j)][kb * 8]; \
    x##j -= h0*Lj[0] + h1*Lj[1] + h2*Lj[2] + h3*Lj[3] + h4*Lj[4] + h5*Lj[5] + h6*Lj[6] + h7*Lj[7]; }
                            UPDJ(0) UPDJ(1) UPDJ(2) UPDJ(3) UPDJ(4) UPDJ(5) UPDJ(6) UPDJ(7)
#undef UPDJ
                        }
                        {
                            const int b8 = b * 8;
                            x0 *= rs[b8 + 0];
                            x1 = (x1 - x0*P[b8+1][b8+0]) * rs[b8+1];
                            x2 = (x2 - x0*P[b8+2][b8+0] - x1*P[b8+2][b8+1]) * rs[b8+2];
                            x3 = (x3 - x0*P[b8+3][b8+0] - x1*P[b8+3][b8+1] - x2*P[b8+3][b8+2]) * rs[b8+3];
                            x4 = (x4 - x0*P[b8+4][b8+0] - x1*P[b8+4][b8+1] - x2*P[b8+4][b8+2]
                                     - x3*P[b8+4][b8+3]) * rs[b8+4];
                            x5 = (x5 - x0*P[b8+5][b8+0] - x1*P[b8+5][b8+1] - x2*P[b8+5][b8+2]
                                     - x3*P[b8+5][b8+3] - x4*P[b8+5][b8+4]) * rs[b8+5];
                            x6 = (x6 - x0*P[b8+6][b8+0] - x1*P[b8+6][b8+1] - x2*P[b8+6][b8+2]
                                     - x3*P[b8+6][b8+3] - x4*P[b8+6][b8+4] - x5*P[b8+6][b8+5]) * rs[b8+6];
                            x7 = (x7 - x0*P[b8+7][b8+0] - x1*P[b8+7][b8+1] - x2*P[b8+7][b8+2]
                                     - x3*P[b8+7][b8+3] - x4*P[b8+7][b8+4] - x5*P[b8+7][b8+5]
                                     - x6*P[b8+7][b8+6]) * rs[b8+7];
                        }
                        gb[0] = x0; gb[1] = x1; gb[2] = x2; gb[3] = x3;
                        gb[4] = x4; gb[5] = x5; gb[6] = x6; gb[7] = x7;
                    }
                }
            }
        }
        grid_bar(barid++);

        // trailing SYRK update (all blocks)
        if (nr > 0) {
            int nt = nr >> 6;
            int ntiles = nt * (nt + 1) / 2;
            for (int t = bid; t < ntiles; t += CHB) {
                __syncthreads();
                int bi = 0;
                while ((bi + 1) * (bi + 2) / 2 <= t) bi++;
                int bj = t - bi * (bi + 1) / 2;
                for (int idx = tid; idx < 4096; idx += 256) {
                    int i = idx >> 6, j = idx & 63;
                    As[i][j] = g_S[(size_t)(o2 + bi * 64 + i) * R_ + o + j];
                    Bs[i][j] = g_S[(size_t)(o2 + bj * 64 + i) * R_ + o + j];
                }
                __syncthreads();
                int tx = tid & 15, ty = tid >> 4;
                float acc[4][4];
#pragma unroll
                for (int r = 0; r < 4; r++)
#pragma unroll
                    for (int c = 0; c < 4; c++) acc[r][c] = 0.f;
#pragma unroll 8
                for (int k = 0; k < 64; k++) {
                    float a[4], b[4];
#pragma unroll
                    for (int r = 0; r < 4; r++) a[r] = As[ty * 4 + r][k];
#pragma unroll
                    for (int c = 0; c < 4; c++) b[c] = Bs[tx * 4 + c][k];
#pragma unroll
                    for (int r = 0; r < 4; r++)
#pragma unroll
                        for (int c = 0; c < 4; c++) acc[r][c] = fmaf(a[r], b[c], acc[r][c]);
                }
#pragma unroll
                for (int r = 0; r < 4; r++)
#pragma unroll
                    for (int c = 0; c < 4; c++)
                        g_S[(size_t)(o2 + bi * 64 + ty * 4 + r) * R_ + o2 + bj * 64 + tx * 4 + c] -= acc[r][c];
            }
        }
        grid_bar(barid++);
    }
}

// ---------------- ||eps||^2 + per-class argmax (block pre-reduced) ----------------
__global__ void sq_kernel(const float* __restrict__ eps) {   // grid 3125 x 256
    __shared__ unsigned long long keys[32];
    int tid = threadIdx.x, w = tid >> 5, lane = tid & 31;
    int rowbase = blockIdx.x * 32;
#pragma unroll
    for (int pr = 0; pr < 2; pr++) {
        int r0 = rowbase + w * 4 + pr * 2;
        const float4* p0 = (const float4*)(eps + (size_t)r0 * R_);
        const float4* p1 = (const float4*)(eps + (size_t)(r0 + 1) * R_);
        float s0 = 0.f, s1 = 0.f;
#pragma unroll
        for (int it = 0; it < 8; it++) {
            float4 a = p0[lane + it * 32];
            float4 b = p1[lane + it * 32];
            s0 = fmaf(a.x, a.x, fmaf(a.y, a.y, fmaf(a.z, a.z, fmaf(a.w, a.w, s0))));
            s1 = fmaf(b.x, b.x, fmaf(b.y, b.y, fmaf(b.z, b.z, fmaf(b.w, b.w, s1))));
        }
#pragma unroll
        for (int o = 16; o; o >>= 1) {
            s0 += __shfl_xor_sync(0xffffffffu, s0, o);
            s1 += __shfl_xor_sync(0xffffffffu, s1, o);
        }
        if (lane == 0) {
            int c0 = r0 / S_, c1 = (r0 + 1) / S_;
            unsigned i0 = (unsigned)(r0 - c0 * S_), i1 = (unsigned)(r0 + 1 - c1 * S_);
            keys[w * 4 + pr * 2] =
                ((unsigned long long)__float_as_uint(s0) << 32) | (unsigned long long)(0xFFFFFFFFu - i0);
            keys[w * 4 + pr * 2 + 1] =
                ((unsigned long long)__float_as_uint(s1) << 32) | (unsigned long long)(0xFFFFFFFFu - i1);
        }
    }
    __syncthreads();
    if (tid == 0) {
        int c0 = rowbase / S_;
        unsigned long long m0 = 0ull, m1 = 0ull;
        for (int i = 0; i < 32; i++) {
            int cls = (rowbase + i) / S_;
            unsigned long long k = keys[i];
            if (cls == c0) { if (k > m0) m0 = k; }
            else           { if (k > m1) m1 = k; }
        }
        atomicMax(&g_amax[c0], m0);
        if (m1) atomicMax(&g_amax[c0 + 1], m1);
    }
}

__global__ void gather_kernel(const float* __restrict__ eps) {
    int c = blockIdx.x;
    unsigned s = 0xFFFFFFFFu - (unsigned)(g_amax[c] & 0xFFFFFFFFull);
    const float4* src = (const float4*)(eps + ((size_t)c * S_ + s) * R_);
    ((float4*)(g_eps_sel + c * R_))[threadIdx.x] = src[threadIdx.x];
}

// ---------------- vos = mu + L @ eps_sel ----------------
__global__ void vos_kernel() {                  // grid 16 x 256
    __shared__ float e[C_][R_];
    int tid = threadIdx.x;
    for (int i = tid; i < C_ * R_; i += 256) ((float*)e)[i] = g_eps_sel[i];
    __syncthreads();
    int w = tid >> 5, lane = tid & 31;
    for (int rr = 0; rr < 8; rr++) {
        int i = blockIdx.x * 64 + rr * 8 + w;
        const float* Lr = g_S + (size_t)i * R_;
        float p[C_];
#pragma unroll
        for (int c = 0; c < C_; c++) p[c] = 0.f;
        for (int j = lane; j <= i; j += 32) {
            float Lv = Lr[j];
#pragma unroll
            for (int c = 0; c < C_; c++) p[c] = fmaf(Lv, e[c][j], p[c]);
        }
#pragma unroll
        for (int c = 0; c < C_; c++) {
            float v = p[c];
#pragma unroll
            for (int o = 16; o; o >>= 1) v += __shfl_xor_sync(0xffffffffu, v, o);
            if (lane == 0) g_vos[c * R_ + i] = g_mu[c * R_ + i] + v;
        }
    }
}

// ---------------- scores + focal (cls path) ----------------
__global__ void scores_cls_kernel(const float* __restrict__ X, const float* __restrict__ W,
                                  const float* __restrict__ b, const int* __restrict__ labels) {
    __shared__ float red[C_][8];
    __shared__ float srow[C_];
    int row = blockIdx.x, tid = threadIdx.x;
    float acc[C_];
#pragma unroll
    for (int c = 0; c < C_; c++) acc[c] = 0.f;
    const float* x = X + (size_t)row * R_;
    for (int r = tid; r < R_; r += 256) {
        float xv = x[r];
#pragma unroll
        for (int c = 0; c < C_; c++) acc[c] = fmaf(xv, W[c * R_ + r], acc[c]);
    }
#pragma unroll
    for (int c = 0; c < C_; c++) {
        float v = acc[c];
#pragma unroll
        for (int o = 16; o; o >>= 1) v += __shfl_xor_sync(0xffffffffu, v, o);
        acc[c] = v;
    }
    int w = tid >> 5, lane = tid & 31;
    if (lane == 0)
#pragma unroll
        for (int c = 0; c < C_; c++) red[c][w] = acc[c];
    __syncthreads();
    if (tid < C_) {
        float s = red[tid][0];
#pragma unroll
        for (int ww = 1; ww < 8; ww++) s += red[tid][ww];
        s += b[tid];
        g_scores[row * C_ + tid] = s;
        srow[tid] = s;
    }
    __syncthreads();
    if (tid == 0) {
        int lab = labels[row];
        float fs = 0.f;
#pragma unroll
        for (int c = 0; c < C_; c++) {
            float xv = srow[c];
            float tt = (c == lab) ? 1.f : 0.f;
            float ce = fmaxf(xv, 0.f) - xv * tt + log1pf(expf(-fabsf(xv)));
            float pp = 1.f / (1.f + expf(-xv));
            float pt = pp * tt + (1.f - pp) * (1.f - tt);
            float at = 0.25f * tt + 0.75f * (1.f - tt);
            float om = 1.f - pt;
            fs += at * ce * om * om;
        }
        g_focal[row] = fs;
    }
}

// ---------------- scores_vos ----------------
__global__ void scores_vos_kernel(const float* __restrict__ W, const float* __restrict__ b) {
    __shared__ float red[C_][8];
    int row = blockIdx.x, tid = threadIdx.x;
    float acc[C_];
#pragma unroll
    for (int c = 0; c < C_; c++) acc[c] = 0.f;
    const float* x = g_vos + (size_t)row * R_;
    for (int r = tid; r < R_; r += 256) {
        float xv = x[r];
#pragma unroll
        for (int c = 0; c < C_; c++) acc[c] = fmaf(xv, W[c * R_ + r], acc[c]);
    }
#pragma unroll
    for (int c = 0; c < C_; c++) {
        float v = acc[c];
#pragma unroll
        for (int o = 16; o; o >>= 1) v += __shfl_xor_sync(0xffffffffu, v, o);
        acc[c] = v;
    }
    int w = tid >> 5, lane = tid & 31;
    if (lane == 0)
#pragma unroll
        for (int c = 0; c < C_; c++) red[c][w] = acc[c];
    __syncthreads();
    if (tid < C_) {
        float s = red[tid][0];
#pragma unroll
        for (int ww = 1; ww < 8; ww++) s += red[tid][ww];
        g_scores_vos[row * C_ + tid] = s + b[tid];
    }
}

// ---------------- energy -> MLP -> BCE + focal reduction ----------------
__global__ void final_kernel(const float* __restrict__ w_e, const float* __restrict__ W1,
                             const float* __restrict__ b1, const float* __restrict__ W2,
                             const float* __restrict__ b2, float* __restrict__ out) {
    __shared__ float we[C_];
    __shared__ float bce[544];
    __shared__ float foc[N_];
    int tid = threadIdx.x;                      // 544 threads
    if (tid < C_) we[tid] = fmaxf(w_e[tid], 0.f);
    for (int i = tid; i < N_; i += 544) foc[i] = g_focal[i];
    __syncthreads();
    float v = 0.f;
    if (tid < N_ + C_) {
        const float* row = (tid < N_) ? (g_scores + tid * C_) : (g_scores_vos + (tid - N_) * C_);
        float m = row[0];
#pragma unroll
        for (int c = 1; c < C_; c++) m = fmaxf(m, row[c]);
        float ssum = 0.f;
#pragma unroll
        for (int c = 0; c < C_; c++) ssum += expf(row[c] - m) * we[c];
        float e = m + logf(ssum);
        float lg = 0.f;
        for (int j = 0; j < 512; j++) lg = fmaf(fmaxf(fmaf(e, W1[j], b1[j]), 0.f), W2[j], lg);
        lg += b2[0];
        float y = (tid < N_) ? 1.f : 0.f;
        v = fmaxf(lg, 0.f) - lg * y + log1pf(expf(-fabsf(lg)));
    }
    bce[tid] = v;
    __syncthreads();
    if (tid == 0) {
        float bs = 0.f;
        for (int i = 0; i < N_ + C_; i++) bs += bce[i];
        float fsum = 0.f;
        for (int i = 0; i < N_; i++) fsum += foc[i];
        out[0] = fsum / (float)N_;
        out[1] = 0.1f * bs / (float)(N_ + C_);
    }
}

// ---------------- launch ----------------
extern "C" void kernel_launch(void* const* d_in, const int* in_sizes, int n_in,
                              void* d_out, int out_size) {
    const float* box     = (const float*)d_in[0];
    const int*   labels  = (const int*)d_in[1];
    const float* id_data = (const float*)d_in[2];
    const float* W_pred  = (const float*)d_in[4];
    const float* b_pred  = (const float*)d_in[5];
    const float* w_e     = (const float*)d_in[6];
    const float* dW1     = (const float*)d_in[7];
    const float* db1     = (const float*)d_in[8];
    const float* dW2     = (const float*)d_in[9];
    const float* db2     = (const float*)d_in[10];
    const float* eps     = (const float*)d_in[11];
    float* out = (float*)d_out;
    (void)in_sizes; (void)n_in; (void)out_size;

    cudaFuncSetAttribute(syrk_kernel, cudaFuncAttributeMaxDynamicSharedMemorySize, SYRK_SMEM);

    order_mu_kernel<<<41, 256>>>(labels, id_data, box);     // 1
    matD_kernel<<<MP, 256>>>(id_data, box);                 // 2
    syrk_kernel<<<dim3(36, KSPLIT), 256, SYRK_SMEM>>>();    // 3
    chol_kernel<<<CHB, 256>>>();                            // 4  <- profiled
    sq_kernel<<<3125, 256>>>(eps);                          // 5
    gather_kernel<<<C_, 256>>>(eps);                        // 6
    vos_kernel<<<16, 256>>>();                              // 7
    scores_cls_kernel<<<N_, 256>>>(box, W_pred, b_pred, labels); // 8
    scores_vos_kernel<<<C_, 256>>>(W_pred, b_pred);         // 9
    final_kernel<<<1, 544>>>(w_e, dW1, db1, dW2, db2, out); // 10
}

// round 17
// speedup vs baseline: 1.1705x; 1.1705x over previous
#include <cuda_runtime.h>
#include <math.h>

#define C_ 10
#define Q_ 1000
#define R_ 1024
#define N_ 512
#define S_ 10000
#define M_ 10000          // C_*Q_
#define MP 10240          // padded rows
#define KSPLIT 8
#define CHUNKP 1280       // MP/KSPLIT
#define SSTR 136          // SYRK SMEM row stride (floats)
#define TILEF (32*SSTR)
#define SYRK_SMEM (4*TILEF*4)   // 69632 bytes
#define CHB 120           // persistent-Cholesky blocks

// ---------------- static device scratch ----------------
static __device__ float g_Gp[KSPLIT][R_ * R_];
static __device__ float g_S[R_ * R_];
static __device__ float g_mup[CHB][R_];
static __device__ float g_mu[C_ * R_];
static __device__ float g_scores[N_ * C_];
static __device__ float g_scores_vos[C_ * C_];
static __device__ float g_eps_sel[C_ * R_];
static __device__ float g_vos[C_ * R_];
static __device__ float g_focal[N_];
static __device__ const float* g_rowsrc[MP];
static __device__ unsigned long long g_amax[C_];
static __device__ int   g_bars[64];
static __device__ float g_zero[R_];     // zero-init, NEVER written -> padded rows

// ---------------- kernel 1: ordering + counts + row-source table + state reset ----------------
__global__ void order_kernel(const int* __restrict__ labels,
                             const float* __restrict__ id_data,
                             const float* __restrict__ box) {
    __shared__ int labs[N_];
    __shared__ int sorder[C_ * N_];
    __shared__ int scnt[C_];
    int tid = threadIdx.x;                    // 512 threads
    labs[tid] = labels[tid];
    if (tid < C_) g_amax[tid] = 0ull;
    if (tid < 64) g_bars[tid] = 0;
    __syncthreads();
    int lab = labs[tid];
    int pos = 0;
    for (int j = 0; j < tid; j++) pos += (labs[j] == lab) ? 1 : 0;
    sorder[lab * N_ + pos] = tid;
    if (tid < C_) {
        int cnt = 0;
        for (int j = 0; j < N_; j++) cnt += (labs[j] == tid) ? 1 : 0;
        scnt[tid] = cnt;
    }
    __syncthreads();
    for (int row = tid; row < MP; row += 512) {
        const float* src;
        if (row >= M_) src = g_zero;
        else {
            int c = row / Q_, q = row - c * Q_;
            int k = scnt[c];
            if (q < Q_ - k) src = id_data + (size_t)(c * Q_ + q + k) * R_;
            else            src = box + (size_t)sorder[c * N_ + q - (Q_ - k)] * R_;
        }
        g_rowsrc[row] = src;
    }
}

// ---------------- kernel 2: tf32 tensor-core SYRK via row indirection ----------------
__device__ __forceinline__ unsigned f2tf(float x) {
    unsigned r; asm("cvt.rna.tf32.f32 %0, %1;" : "=r"(r) : "f"(x)); return r;
}
__device__ __forceinline__ void mma_tf32(float* d, const unsigned* a, const unsigned* b) {
    asm volatile(
        "mma.sync.aligned.m16n8k8.row.col.f32.tf32.tf32.f32 "
        "{%0,%1,%2,%3}, {%4,%5,%6,%7}, {%8,%9}, {%0,%1,%2,%3};\n"
        : "+f"(d[0]), "+f"(d[1]), "+f"(d[2]), "+f"(d[3])
        : "r"(a[0]), "r"(a[1]), "r"(a[2]), "r"(a[3]), "r"(b[0]), "r"(b[1]));
}
__device__ __forceinline__ void cpasync16(unsigned saddr, const void* g) {
    asm volatile("cp.async.ca.shared.global [%0], [%1], 16;\n" :: "r"(saddr), "l"(g));
}
__device__ __forceinline__ void cp_commit() { asm volatile("cp.async.commit_group;\n"); }
__device__ __forceinline__ void cp_wait0()  { asm volatile("cp.async.wait_group 0;\n"); }

__global__ __launch_bounds__(256, 2) void syrk_kernel() {
    extern __shared__ float smem[];
    int t = blockIdx.x;
    int bi = 0;
    while ((bi + 1) * (bi + 2) / 2 <= t) bi++;
    int bj = t - bi * (bi + 1) / 2;
    bool diag = (bi == bj);

    int tid = threadIdx.x;
    int wid = tid >> 5, lane = tid & 31;
    int wy = wid & 1, wx = wid >> 1;
    int g = lane >> 2, tg = lane & 3;
    int lr = tid >> 3, lc = tid & 7;
    int m0 = blockIdx.y * CHUNKP;

    float acc[4][4][4];
#pragma unroll
    for (int mf = 0; mf < 4; mf++)
#pragma unroll
        for (int nf = 0; nf < 4; nf++)
#pragma unroll
            for (int q = 0; q < 4; q++) acc[mf][nf][q] = 0.f;

    auto issue = [&](int b, int mb) {
        float* SA = smem + b * (2 * TILEF);
        float* SB = SA + TILEF;
        const float* gr = g_rowsrc[mb + lr];
        unsigned sA = (unsigned)__cvta_generic_to_shared(SA + lr * SSTR);
        unsigned sB = (unsigned)__cvta_generic_to_shared(SB + lr * SSTR);
#pragma unroll
        for (int i = 0; i < 4; i++) {
            int c0 = (lc + 8 * i) * 4;
            cpasync16(sA + c0 * 4, gr + bi * 128 + c0);
            if (!diag) cpasync16(sB + c0 * 4, gr + bj * 128 + c0);
        }
        cp_commit();
    };

    issue(0, m0);
    for (int s = 0; s < 40; s++) {
        int b = s & 1;
        cp_wait0();
        __syncthreads();
        if (s < 39) issue(b ^ 1, m0 + (s + 1) * 32);
        float* SA = smem + b * (2 * TILEF);
        float* SB = diag ? SA : (SA + TILEF);
#pragma unroll
        for (int ks = 0; ks < 4; ks++) {
            int k0 = ks * 8;
            unsigned af[4][4], bf[4][2];
#pragma unroll
            for (int mf = 0; mf < 4; mf++) {
                int r0 = wy * 64 + mf * 16;
                af[mf][0] = f2tf(SA[(k0 + tg) * SSTR + r0 + g]);
                af[mf][1] = f2tf(SA[(k0 + tg) * SSTR + r0 + g + 8]);
                af[mf][2] = f2tf(SA[(k0 + tg + 4) * SSTR + r0 + g]);
                af[mf][3] = f2tf(SA[(k0 + tg + 4) * SSTR + r0 + g + 8]);
            }
#pragma unroll
            for (int nf = 0; nf < 4; nf++) {
                int c0 = wx * 32 + nf * 8;
                bf[nf][0] = f2tf(SB[(k0 + tg) * SSTR + c0 + g]);
                bf[nf][1] = f2tf(SB[(k0 + tg + 4) * SSTR + c0 + g]);
            }
#pragma unroll
            for (int mf = 0; mf < 4; mf++)
#pragma unroll
                for (int nf = 0; nf < 4; nf++)
                    mma_tf32(acc[mf][nf], af[mf], bf[nf]);
        }
        __syncthreads();
    }
    float* gp = g_Gp[blockIdx.y];
#pragma unroll
    for (int mf = 0; mf < 4; mf++) {
        int r0 = bi * 128 + wy * 64 + mf * 16 + g;
#pragma unroll
        for (int nf = 0; nf < 4; nf++) {
            int c0 = bj * 128 + wx * 32 + nf * 8 + 2 * tg;
            *(float2*)&gp[(size_t)r0 * R_ + c0]       = make_float2(acc[mf][nf][0], acc[mf][nf][1]);
            *(float2*)&gp[(size_t)(r0 + 8) * R_ + c0] = make_float2(acc[mf][nf][2], acc[mf][nf][3]);
        }
    }
}

// ---------------- kernel 3: ||eps||^2 + per-class argmax (block pre-reduced) ----------------
__global__ void sq_kernel(const float* __restrict__ eps) {   // grid 3125 x 256
    __shared__ unsigned long long keys[32];
    int tid = threadIdx.x, w = tid >> 5, lane = tid & 31;
    int rowbase = blockIdx.x * 32;
#pragma unroll
    for (int pr = 0; pr < 2; pr++) {
        int r0 = rowbase + w * 4 + pr * 2;
        const float4* p0 = (const float4*)(eps + (size_t)r0 * R_);
        const float4* p1 = (const float4*)(eps + (size_t)(r0 + 1) * R_);
        float s0 = 0.f, s1 = 0.f;
#pragma unroll
        for (int it = 0; it < 8; it++) {
            float4 a = p0[lane + it * 32];
            float4 b = p1[lane + it * 32];
            s0 = fmaf(a.x, a.x, fmaf(a.y, a.y, fmaf(a.z, a.z, fmaf(a.w, a.w, s0))));
            s1 = fmaf(b.x, b.x, fmaf(b.y, b.y, fmaf(b.z, b.z, fmaf(b.w, b.w, s1))));
        }
#pragma unroll
        for (int o = 16; o; o >>= 1) {
            s0 += __shfl_xor_sync(0xffffffffu, s0, o);
            s1 += __shfl_xor_sync(0xffffffffu, s1, o);
        }
        if (lane == 0) {
            int c0 = r0 / S_, c1 = (r0 + 1) / S_;
            unsigned i0 = (unsigned)(r0 - c0 * S_), i1 = (unsigned)(r0 + 1 - c1 * S_);
            keys[w * 4 + pr * 2] =
                ((unsigned long long)__float_as_uint(s0) << 32) | (unsigned long long)(0xFFFFFFFFu - i0);
            keys[w * 4 + pr * 2 + 1] =
                ((unsigned long long)__float_as_uint(s1) << 32) | (unsigned long long)(0xFFFFFFFFu - i1);
        }
    }
    __syncthreads();
    if (tid == 0) {
        int c0 = rowbase / S_;
        unsigned long long m0 = 0ull, m1 = 0ull;
        for (int i = 0; i < 32; i++) {
            int cls = (rowbase + i) / S_;
            unsigned long long k = keys[i];
            if (cls == c0) { if (k > m0) m0 = k; }
            else           { if (k > m1) m1 = k; }
        }
        atomicMax(&g_amax[c0], m0);
        if (m1) atomicMax(&g_amax[c0 + 1], m1);
    }
}

// ---------------- kernel 4: persistent mu + sigma + blocked Cholesky ----------------
__device__ __forceinline__ void grid_bar(int id) {
    __syncthreads();
    if (threadIdx.x == 0) {
        __threadfence();
        atomicAdd(&g_bars[id], 1);
        while (*(volatile int*)&g_bars[id] < CHB) { }
        __threadfence();
    }
    __syncthreads();
}

__global__ __launch_bounds__(256) void chol_kernel() {
    __shared__ float P[64][65];
    __shared__ float rs[64];        // 1/L[k][k]
    __shared__ float As[64][65];
    __shared__ float Bs[64][65];
    int bid = blockIdx.x, tid = threadIdx.x;
    int wid = tid >> 5, lane = tid & 31;

    // ---- phase A: per-class mean partials (coalesced via rowsrc) ----
    {
        int c = bid / 12, z = bid - c * 12;           // 10 classes x 12 blocks
        int r0 = z * 84, r1 = r0 + 84; if (r1 > Q_) r1 = Q_;
        float4 s = make_float4(0.f, 0.f, 0.f, 0.f);
        for (int r = r0; r < r1; r++) {
            float4 v = ((const float4*)g_rowsrc[c * Q_ + r])[tid];
            s.x += v.x; s.y += v.y; s.z += v.z; s.w += v.w;
        }
        ((float4*)g_mup[bid])[tid] = s;
    }
    grid_bar(0);
    // ---- phase B: mu reduce ----
    if (bid < 40) {
        int gid = bid * 256 + tid;
        int c = gid >> 10, r = gid & 1023;
        float s = 0.f;
#pragma unroll
        for (int z = 0; z < 12; z++) s += g_mup[c * 12 + z][r];
        g_mu[gid] = s * (1.f / (float)Q_);
    }
    grid_bar(1);
    // ---- phase C: sigma (lower) = (sum Gp - Q*sum_c mu mu^T)/M + 1e-4 I ----
    for (int i = bid; i < R_; i += CHB) {
        size_t ro = (size_t)i * R_;
        float mi[C_];
#pragma unroll
        for (int c = 0; c < C_; c++) mi[c] = g_mu[c * R_ + i];
        for (int j = tid; j <= i; j += 256) {
            float s = 0.f;
#pragma unroll
            for (int z = 0; z < KSPLIT; z++) s += g_Gp[z][ro + j];
            float corr = 0.f;
#pragma unroll
            for (int c = 0; c < C_; c++) corr += mi[c] * g_mu[c * R_ + j];
            float v = (s - (float)Q_ * corr) * (1.f / (float)M_);
            if (i == j) v += 1e-4f;
            g_S[ro + j] = v;
        }
    }
    grid_bar(2);

    // ---- phase D: blocked Cholesky, 16 panels of 64 ----
    int barid = 3;
    for (int p = 0; p < 16; p++) {
        int o = p * 64, o2 = o + 64, nr = R_ - o2;

        if (bid < 4) {
            for (int idx = tid; idx < 4096; idx += 256) {
                int i = idx >> 6, j = idx & 63;
                P[i][j] = (j <= i) ? g_S[(size_t)(o + i) * R_ + o + j] : 0.f;
            }
            __syncthreads();
            // micro-blocked potf2: 8 rank-8 steps
            for (int m = 0; m < 8; m++) {
                int q = m * 8;
                if (wid == 0) {
                    // strip factor (cols q..q+7), raw rank-1 confined to strip
                    for (int kk = 0; kk < 8; kk++) {
                        int k = q + kk;
                        float d = P[k][k];
                        float rd = __frcp_rn(d);
                        if (lane == 0) rs[k] = rsqrtf(d);
                        for (int i = k + 1 + lane; i < 64; i += 32) {
                            float pik = P[i][k];
#pragma unroll
                            for (int c = 1; c < 8; c++)
                                if (kk + c < 8)
                                    P[i][q + kk + c] -= pik * P[k][q + kk + c] * rd;
                        }
                        __syncwarp();
                    }
                    // scale strip columns -> final L values
#pragma unroll
                    for (int kk = 0; kk < 8; kk++) {
                        int k = q + kk;
                        float r = rs[k];
                        for (int i = k + lane; i < 64; i += 32) P[i][k] *= r;
                    }
                }
                __syncthreads();
                // rank-8 trailing update within panel
                int base = q + 8;
                for (int i = base + wid; i < 64; i += 8) {
                    float Li[8];
#pragma unroll
                    for (int kk = 0; kk < 8; kk++) Li[kk] = P[i][q + kk];
                    for (int j = base + lane; j <= i; j += 32) {
                        float a = P[i][j];
#pragma unroll
                        for (int kk = 0; kk < 8; kk++) a -= Li[kk] * P[j][q + kk];
                        P[i][j] = a;
                    }
                }
                __syncthreads();
            }
            if (bid == 0) {
                for (int idx = tid; idx < 4096; idx += 256) {
                    int i = idx >> 6, j = idx & 63;
                    if (j <= i) g_S[(size_t)(o + i) * R_ + o + j] = P[i][j];
                }
            }
            // TRSM rows (named-register 8-col blocks)
            if (nr > 0) {
                int rr = bid * 256 + tid;
                if (rr < nr) {
                    int r = o2 + rr;
                    float* gptr = g_S + (size_t)r * R_ + o;
#pragma unroll
                    for (int b = 0; b < 8; b++) {
                        float* gb = gptr + b * 8;
                        float x0 = gb[0], x1 = gb[1], x2 = gb[2], x3 = gb[3],
                              x4 = gb[4], x5 = gb[5], x6 = gb[6], x7 = gb[7];
#pragma unroll
                        for (int kb = 0; kb < b; kb++) {
                            const float* hp = gptr + kb * 8;
                            float h0 = hp[0], h1 = hp[1], h2 = hp[2], h3 = hp[3],
                                  h4 = hp[4], h5 = hp[5], h6 = hp[6], h7 = hp[7];
#define UPDJ(j) { const float* Lj = &P[b * 8 + (j)][kb * 8]; \
    x##j -= h0*Lj[0] + h1*Lj[1] + h2*Lj[2] + h3*Lj[3] + h4*Lj[4] + h5*Lj[5] + h6*Lj[6] + h7*Lj[7]; }
                            UPDJ(0) UPDJ(1) UPDJ(2) UPDJ(3) UPDJ(4) UPDJ(5) UPDJ(6) UPDJ(7)
#undef UPDJ
                        }
                        {
                            const int b8 = b * 8;
                            x0 *= rs[b8 + 0];
                            x1 = (x1 - x0*P[b8+1][b8+0]) * rs[b8+1];
                            x2 = (x2 - x0*P[b8+2][b8+0] - x1*P[b8+2][b8+1]) * rs[b8+2];
                            x3 = (x3 - x0*P[b8+3][b8+0] - x1*P[b8+3][b8+1] - x2*P[b8+3][b8+2]) * rs[b8+3];
                            x4 = (x4 - x0*P[b8+4][b8+0] - x1*P[b8+4][b8+1] - x2*P[b8+4][b8+2]
                                     - x3*P[b8+4][b8+3]) * rs[b8+4];
                            x5 = (x5 - x0*P[b8+5][b8+0] - x1*P[b8+5][b8+1] - x2*P[b8+5][b8+2]
                                     - x3*P[b8+5][b8+3] - x4*P[b8+5][b8+4]) * rs[b8+5];
                            x6 = (x6 - x0*P[b8+6][b8+0] - x1*P[b8+6][b8+1] - x2*P[b8+6][b8+2]
                                     - x3*P[b8+6][b8+3] - x4*P[b8+6][b8+4] - x5*P[b8+6][b8+5]) * rs[b8+6];
                            x7 = (x7 - x0*P[b8+7][b8+0] - x1*P[b8+7][b8+1] - x2*P[b8+7][b8+2]
                                     - x3*P[b8+7][b8+3] - x4*P[b8+7][b8+4] - x5*P[b8+7][b8+5]
                                     - x6*P[b8+7][b8+6]) * rs[b8+7];
                        }
                        gb[0] = x0; gb[1] = x1; gb[2] = x2; gb[3] = x3;
                        gb[4] = x4; gb[5] = x5; gb[6] = x6; gb[7] = x7;
                    }
                }
            }
        }
        grid_bar(barid++);

        if (nr > 0) {
            int nt = nr >> 6;
            int ntiles = nt * (nt + 1) / 2;
            for (int t = bid; t < ntiles; t += CHB) {
                __syncthreads();
                int bi = 0;
                while ((bi + 1) * (bi + 2) / 2 <= t) bi++;
                int bj = t - bi * (bi + 1) / 2;
                for (int idx = tid; idx < 4096; idx += 256) {
                    int i = idx >> 6, j = idx & 63;
                    As[i][j] = g_S[(size_t)(o2 + bi * 64 + i) * R_ + o + j];
                    Bs[i][j] = g_S[(size_t)(o2 + bj * 64 + i) * R_ + o + j];
                }
                __syncthreads();
                int tx = tid & 15, ty = tid >> 4;
                float acc[4][4];
#pragma unroll
                for (int r = 0; r < 4; r++)
#pragma unroll
                    for (int c = 0; c < 4; c++) acc[r][c] = 0.f;
#pragma unroll 8
                for (int k = 0; k < 64; k++) {
                    float a[4], b[4];
#pragma unroll
                    for (int r = 0; r < 4; r++) a[r] = As[ty * 4 + r][k];
#pragma unroll
                    for (int c = 0; c < 4; c++) b[c] = Bs[tx * 4 + c][k];
#pragma unroll
                    for (int r = 0; r < 4; r++)
#pragma unroll
                        for (int c = 0; c < 4; c++) acc[r][c] = fmaf(a[r], b[c], acc[r][c]);
                }
#pragma unroll
                for (int r = 0; r < 4; r++)
#pragma unroll
                    for (int c = 0; c < 4; c++)
                        g_S[(size_t)(o2 + bi * 64 + ty * 4 + r) * R_ + o2 + bj * 64 + tx * 4 + c] -= acc[r][c];
            }
        }
        grid_bar(barid++);
    }
}

// ---------------- gather selected eps ----------------
__global__ void gather_kernel(const float* __restrict__ eps) {
    int c = blockIdx.x;
    unsigned s = 0xFFFFFFFFu - (unsigned)(g_amax[c] & 0xFFFFFFFFull);
    const float4* src = (const float4*)(eps + ((size_t)c * S_ + s) * R_);
    ((float4*)(g_eps_sel + c * R_))[threadIdx.x] = src[threadIdx.x];
}

// ---------------- vos = mu + L @ eps_sel ----------------
__global__ void vos_kernel() {                  // grid 16 x 256
    __shared__ float e[C_][R_];
    int tid = threadIdx.x;
    for (int i = tid; i < C_ * R_; i += 256) ((float*)e)[i] = g_eps_sel[i];
    __syncthreads();
    int w = tid >> 5, lane = tid & 31;
    for (int rr = 0; rr < 8; rr++) {
        int i = blockIdx.x * 64 + rr * 8 + w;
        const float* Lr = g_S + (size_t)i * R_;
        float p[C_];
#pragma unroll
        for (int c = 0; c < C_; c++) p[c] = 0.f;
        for (int j = lane; j <= i; j += 32) {
            float Lv = Lr[j];
#pragma unroll
            for (int c = 0; c < C_; c++) p[c] = fmaf(Lv, e[c][j], p[c]);
        }
#pragma unroll
        for (int c = 0; c < C_; c++) {
            float v = p[c];
#pragma unroll
            for (int o = 16; o; o >>= 1) v += __shfl_xor_sync(0xffffffffu, v, o);
            if (lane == 0) g_vos[c * R_ + i] = g_mu[c * R_ + i] + v;
        }
    }
}

// ---------------- scores + focal (cls path) ----------------
__global__ void scores_cls_kernel(const float* __restrict__ X, const float* __restrict__ W,
                                  const float* __restrict__ b, const int* __restrict__ labels) {
    __shared__ float red[C_][8];
    __shared__ float srow[C_];
    int row = blockIdx.x, tid = threadIdx.x;
    float acc[C_];
#pragma unroll
    for (int c = 0; c < C_; c++) acc[c] = 0.f;
    const float* x = X + (size_t)row * R_;
    for (int r = tid; r < R_; r += 256) {
        float xv = x[r];
#pragma unroll
        for (int c = 0; c < C_; c++) acc[c] = fmaf(xv, W[c * R_ + r], acc[c]);
    }
#pragma unroll
    for (int c = 0; c < C_; c++) {
        float v = acc[c];
#pragma unroll
        for (int o = 16; o; o >>= 1) v += __shfl_xor_sync(0xffffffffu, v, o);
        acc[c] = v;
    }
    int w = tid >> 5, lane = tid & 31;
    if (lane == 0)
#pragma unroll
        for (int c = 0; c < C_; c++) red[c][w] = acc[c];
    __syncthreads();
    if (tid < C_) {
        float s = red[tid][0];
#pragma unroll
        for (int ww = 1; ww < 8; ww++) s += red[tid][ww];
        s += b[tid];
        g_scores[row * C_ + tid] = s;
        srow[tid] = s;
    }
    __syncthreads();
    if (tid == 0) {
        int lab = labels[row];
        float fs = 0.f;
#pragma unroll
        for (int c = 0; c < C_; c++) {
            float xv = srow[c];
            float tt = (c == lab) ? 1.f : 0.f;
            float ce = fmaxf(xv, 0.f) - xv * tt + log1pf(expf(-fabsf(xv)));
            float pp = 1.f / (1.f + expf(-xv));
            float pt = pp * tt + (1.f - pp) * (1.f - tt);
            float at = 0.25f * tt + 0.75f * (1.f - tt);
            float om = 1.f - pt;
            fs += at * ce * om * om;
        }
        g_focal[row] = fs;
    }
}

// ---------------- scores_vos ----------------
__global__ void scores_vos_kernel(const float* __restrict__ W, const float* __restrict__ b) {
    __shared__ float red[C_][8];
    int row = blockIdx.x, tid = threadIdx.x;
    float acc[C_];
#pragma unroll
    for (int c = 0; c < C_; c++) acc[c] = 0.f;
    const float* x = g_vos + (size_t)row * R_;
    for (int r = tid; r < R_; r += 256) {
        float xv = x[r];
#pragma unroll
        for (int c = 0; c < C_; c++) acc[c] = fmaf(xv, W[c * R_ + r], acc[c]);
    }
#pragma unroll
    for (int c = 0; c < C_; c++) {
        float v = acc[c];
#pragma unroll
        for (int o = 16; o; o >>= 1) v += __shfl_xor_sync(0xffffffffu, v, o);
        acc[c] = v;
    }
    int w = tid >> 5, lane = tid & 31;
    if (lane == 0)
#pragma unroll
        for (int c = 0; c < C_; c++) red[c][w] = acc[c];
    __syncthreads();
    if (tid < C_) {
        float s = red[tid][0];
#pragma unroll
        for (int ww = 1; ww < 8; ww++) s += red[tid][ww];
        g_scores_vos[row * C_ + tid] = s + b[tid];
    }
}

// ---------------- energy -> MLP -> BCE + focal reduction ----------------
__global__ void final_kernel(const float* __restrict__ w_e, const float* __restrict__ W1,
                             const float* __restrict__ b1, const float* __restrict__ W2,
                             const float* __restrict__ b2, float* __restrict__ out) {
    __shared__ float we[C_];
    __shared__ float bce[544];
    __shared__ float foc[N_];
    int tid = threadIdx.x;                      // 544 threads
    if (tid < C_) we[tid] = fmaxf(w_e[tid], 0.f);
    for (int i = tid; i < N_; i += 544) foc[i] = g_focal[i];
    __syncthreads();
    float v = 0.f;
    if (tid < N_ + C_) {
        const float* row = (tid < N_) ? (g_scores + tid * C_) : (g_scores_vos + (tid - N_) * C_);
        float m = row[0];
#pragma unroll
        for (int c = 1; c < C_; c++) m = fmaxf(m, row[c]);
        float ssum = 0.f;
#pragma unroll
        for (int c = 0; c < C_; c++) ssum += expf(row[c] - m) * we[c];
        float e = m + logf(ssum);
        float lg = 0.f;
        for (int j = 0; j < 512; j++) lg = fmaf(fmaxf(fmaf(e, W1[j], b1[j]), 0.f), W2[j], lg);
        lg += b2[0];
        float y = (tid < N_) ? 1.f : 0.f;
        v = fmaxf(lg, 0.f) - lg * y + log1pf(expf(-fabsf(lg)));
    }
    bce[tid] = v;
    __syncthreads();
    if (tid == 0) {
        float bs = 0.f;
        for (int i = 0; i < N_ + C_; i++) bs += bce[i];
        float fsum = 0.f;
        for (int i = 0; i < N_; i++) fsum += foc[i];
        out[0] = fsum / (float)N_;
        out[1] = 0.1f * bs / (float)(N_ + C_);
    }
}

// ---------------- launch ----------------
extern "C" void kernel_launch(void* const* d_in, const int* in_sizes, int n_in,
                              void* d_out, int out_size) {
    const float* box     = (const float*)d_in[0];
    const int*   labels  = (const int*)d_in[1];
    const float* id_data = (const float*)d_in[2];
    const float* W_pred  = (const float*)d_in[4];
    const float* b_pred  = (const float*)d_in[5];
    const float* w_e     = (const float*)d_in[6];
    const float* dW1     = (const float*)d_in[7];
    const float* db1     = (const float*)d_in[8];
    const float* dW2     = (const float*)d_in[9];
    const float* db2     = (const float*)d_in[10];
    const float* eps     = (const float*)d_in[11];
    float* out = (float*)d_out;
    (void)in_sizes; (void)n_in; (void)out_size;

    cudaFuncSetAttribute(syrk_kernel, cudaFuncAttributeMaxDynamicSharedMemorySize, SYRK_SMEM);

    order_kernel<<<1, 512>>>(labels, id_data, box);          // 1
    syrk_kernel<<<dim3(36, KSPLIT), 256, SYRK_SMEM>>>();     // 2
    sq_kernel<<<3125, 256>>>(eps);                           // 3
    chol_kernel<<<CHB, 256>>>();                             // 4  <- profiled
    gather_kernel<<<C_, 256>>>(eps);                         // 5
    vos_kernel<<<16, 256>>>();                               // 6
    scores_cls_kernel<<<N_, 256>>>(box, W_pred, b_pred, labels); // 7
    scores_vos_kernel<<<C_, 256>>>(W_pred, b_pred);          // 8
    final_kernel<<<1, 544>>>(w_e, dW1, db1, dW2, db2, out);  // 9
}